// round 5
// baseline (speedup 1.0000x reference)
#include <cuda_runtime.h>
#include <math.h>

#define B_ 4
#define S_ 2048
#define DM_ 1024
#define H_ 16
#define DEPTH_ 64

// ---------------- scratch (device globals; no allocation) ----------------
__device__ float g_Q[(size_t)B_ * S_ * DM_];
__device__ float g_K[(size_t)B_ * S_ * DM_];
__device__ float g_V[(size_t)B_ * S_ * DM_];
__device__ float g_attn[(size_t)B_ * S_ * DM_];

// ---------------- GEMM: C[M,N] = A[M,K] @ W[N,K]^T + bias ----------------
// M = 8192, N = K = 1024. 128x128x16 tile, 256 threads, 8x8 microtile.
#define BM 128
#define BN 128
#define BK 16
#define ASP 132  // smem pitch for [BK][BM] tiles (16B-aligned rows, conflict-mild)

__global__ __launch_bounds__(256, 2) void gemm_bias_kernel(
    const float* __restrict__ A, const float* __restrict__ W,
    const float* __restrict__ bias, float* __restrict__ C) {
  const int K = DM_;
  __shared__ float As[BK * ASP];
  __shared__ float Ws[BK * ASP];

  int tid = threadIdx.x;
  int tx = tid & 15, ty = tid >> 4;
  int rowBase = blockIdx.y * BM;
  int colBase = blockIdx.x * BN;

  // global staging: each thread loads 2 float4 of A and 2 of W per k-tile
  int lin0 = tid, lin1 = tid + 256;
  int r0 = lin0 >> 2, c0 = (lin0 & 3) * 4;
  int r1 = lin1 >> 2, c1 = (lin1 & 3) * 4;

  const float* Ap0 = A + (size_t)(rowBase + r0) * K + c0;
  const float* Ap1 = A + (size_t)(rowBase + r1) * K + c1;
  const float* Wp0 = W + (size_t)(colBase + r0) * K + c0;
  const float* Wp1 = W + (size_t)(colBase + r1) * K + c1;

  float4 ra0 = *(const float4*)Ap0;
  float4 ra1 = *(const float4*)Ap1;
  float4 rw0 = *(const float4*)Wp0;
  float4 rw1 = *(const float4*)Wp1;

  float acc[8][8];
#pragma unroll
  for (int i = 0; i < 8; i++)
#pragma unroll
    for (int j = 0; j < 8; j++) acc[i][j] = 0.f;

  const int NTILE = K / BK;
  for (int kt = 0; kt < NTILE; kt++) {
    // transpose-store staged regs into smem [k][m]
    As[(c0 + 0) * ASP + r0] = ra0.x;
    As[(c0 + 1) * ASP + r0] = ra0.y;
    As[(c0 + 2) * ASP + r0] = ra0.z;
    As[(c0 + 3) * ASP + r0] = ra0.w;
    As[(c1 + 0) * ASP + r1] = ra1.x;
    As[(c1 + 1) * ASP + r1] = ra1.y;
    As[(c1 + 2) * ASP + r1] = ra1.z;
    As[(c1 + 3) * ASP + r1] = ra1.w;
    Ws[(c0 + 0) * ASP + r0] = rw0.x;
    Ws[(c0 + 1) * ASP + r0] = rw0.y;
    Ws[(c0 + 2) * ASP + r0] = rw0.z;
    Ws[(c0 + 3) * ASP + r0] = rw0.w;
    Ws[(c1 + 0) * ASP + r1] = rw1.x;
    Ws[(c1 + 1) * ASP + r1] = rw1.y;
    Ws[(c1 + 2) * ASP + r1] = rw1.z;
    Ws[(c1 + 3) * ASP + r1] = rw1.w;
    __syncthreads();

    if (kt + 1 < NTILE) {  // prefetch next tile into regs
      int off = (kt + 1) * BK;
      ra0 = *(const float4*)(Ap0 + off);
      ra1 = *(const float4*)(Ap1 + off);
      rw0 = *(const float4*)(Wp0 + off);
      rw1 = *(const float4*)(Wp1 + off);
    }

#pragma unroll
    for (int kk = 0; kk < BK; kk++) {
      float4 a0 = *(const float4*)&As[kk * ASP + ty * 4];
      float4 a1 = *(const float4*)&As[kk * ASP + 64 + ty * 4];
      float4 b0 = *(const float4*)&Ws[kk * ASP + tx * 4];
      float4 b1 = *(const float4*)&Ws[kk * ASP + 64 + tx * 4];
      float av[8] = {a0.x, a0.y, a0.z, a0.w, a1.x, a1.y, a1.z, a1.w};
      float bv[8] = {b0.x, b0.y, b0.z, b0.w, b1.x, b1.y, b1.z, b1.w};
#pragma unroll
      for (int i = 0; i < 8; i++)
#pragma unroll
        for (int j = 0; j < 8; j++) acc[i][j] += av[i] * bv[j];
    }
    __syncthreads();
  }

  // epilogue: bias + store (split tile: cols {tx*4..+3} and {64+tx*4..+3})
  float bv0[4], bv1[4];
#pragma unroll
  for (int j = 0; j < 4; j++) {
    bv0[j] = bias[colBase + tx * 4 + j];
    bv1[j] = bias[colBase + 64 + tx * 4 + j];
  }
#pragma unroll
  for (int i = 0; i < 8; i++) {
    int mi = rowBase + ((i < 4) ? (ty * 4 + i) : (64 + ty * 4 + (i - 4)));
    float4 o0 = make_float4(acc[i][0] + bv0[0], acc[i][1] + bv0[1],
                            acc[i][2] + bv0[2], acc[i][3] + bv0[3]);
    float4 o1 = make_float4(acc[i][4] + bv1[0], acc[i][5] + bv1[1],
                            acc[i][6] + bv1[2], acc[i][7] + bv1[3]);
    *(float4*)(C + (size_t)mi * DM_ + colBase + tx * 4) = o0;
    *(float4*)(C + (size_t)mi * DM_ + colBase + 64 + tx * 4) = o1;
  }
}

// ---------------- fused masked-softmax attention (flash-style) ----------------
// One CTA per (b, h, 128-row q tile). 64-key tiles, online softmax.
#define QT 128
#define KT 64
#define PQ 68  // Qs pitch   [q][d]
#define PK 68  // Kt pitch   [d][key]   (transposed K for conflict-free f4 reads)
#define PP 68  // P pitch    [q][key]   (overlays Kt buffer)
#define PVP 68 // Vs pitch   [key][d]

#define ATTN_SMEM_FLOATS (QT * PQ + QT * PP + KT * PVP)
#define ATTN_SMEM_BYTES (ATTN_SMEM_FLOATS * 4)

__global__ __launch_bounds__(256, 2) void attn_kernel(
    const float* __restrict__ Q, const float* __restrict__ Kg,
    const float* __restrict__ Vg, const float* __restrict__ mask,
    float* __restrict__ Out) {
  extern __shared__ float sm[];
  float* Qs = sm;                 // QT x PQ
  float* KP = sm + QT * PQ;       // Kt (KTxPK as [d][key]) then P (QTxPP)
  float* Vs = KP + QT * PP;       // KT x PVP

  int b = blockIdx.z, h = blockIdx.y;
  int q0 = blockIdx.x * QT;
  int tid = threadIdx.x, tx = tid & 15, ty = tid >> 4;
  size_t base = ((size_t)b * S_) * DM_ + (size_t)h * DEPTH_;

  // load Q tile [128 x 64]
  for (int l = tid; l < QT * 16; l += 256) {
    int r = l >> 4, c = (l & 15) * 4;
    *(float4*)&Qs[r * PQ + c] =
        *(const float4*)(Q + base + (size_t)(q0 + r) * DM_ + c);
  }

  float m[8], lsum[8], o[8][4];
#pragma unroll
  for (int i = 0; i < 8; i++) {
    m[i] = -1e30f;
    lsum[i] = 0.f;
    o[i][0] = o[i][1] = o[i][2] = o[i][3] = 0.f;
  }
  const float* maskBase = mask + (size_t)b * S_ * S_ + (size_t)q0 * S_;

  for (int kt = 0; kt < S_ / KT; kt++) {
    int k0 = kt * KT;
    __syncthreads();  // prev PV done reading KP(P)/Vs (also covers Qs on iter 0)

    // load K tile transposed into KP as Kt[d][key]; V row-major
    for (int l = tid; l < KT * 16; l += 256) {
      int key = l >> 4, c = (l & 15) * 4;
      float4 kv = *(const float4*)(Kg + base + (size_t)(k0 + key) * DM_ + c);
      KP[(c + 0) * PK + key] = kv.x;
      KP[(c + 1) * PK + key] = kv.y;
      KP[(c + 2) * PK + key] = kv.z;
      KP[(c + 3) * PK + key] = kv.w;
      *(float4*)&Vs[key * PVP + c] =
          *(const float4*)(Vg + base + (size_t)(k0 + key) * DM_ + c);
    }
    __syncthreads();

    // scores: s[i][j] = Q[ty*8+i][:] . K[tx*4+j][:]
    float s[8][4];
#pragma unroll
    for (int i = 0; i < 8; i++) s[i][0] = s[i][1] = s[i][2] = s[i][3] = 0.f;

#pragma unroll 8
    for (int d = 0; d < DEPTH_; d++) {
      float4 kf = *(const float4*)&KP[d * PK + tx * 4];
#pragma unroll
      for (int i = 0; i < 8; i++) {
        float qv = Qs[(ty * 8 + i) * PQ + d];
        s[i][0] += qv * kf.x;
        s[i][1] += qv * kf.y;
        s[i][2] += qv * kf.z;
        s[i][3] += qv * kf.w;
      }
    }

    // mask + online softmax (row group = 16 lanes sharing ty → width-16 shfl)
#pragma unroll
    for (int i = 0; i < 8; i++) {
      float4 mm =
          *(const float4*)(maskBase + (size_t)(ty * 8 + i) * S_ + k0 + tx * 4);
      s[i][0] = s[i][0] * 0.125f - 1e6f * mm.x;
      s[i][1] = s[i][1] * 0.125f - 1e6f * mm.y;
      s[i][2] = s[i][2] * 0.125f - 1e6f * mm.z;
      s[i][3] = s[i][3] * 0.125f - 1e6f * mm.w;

      float mx = fmaxf(fmaxf(s[i][0], s[i][1]), fmaxf(s[i][2], s[i][3]));
      mx = fmaxf(mx, __shfl_xor_sync(0xffffffffu, mx, 1, 16));
      mx = fmaxf(mx, __shfl_xor_sync(0xffffffffu, mx, 2, 16));
      mx = fmaxf(mx, __shfl_xor_sync(0xffffffffu, mx, 4, 16));
      mx = fmaxf(mx, __shfl_xor_sync(0xffffffffu, mx, 8, 16));

      float mn = fmaxf(m[i], mx);
      float f = __expf(m[i] - mn);
      m[i] = mn;

      float rs = 0.f;
      s[i][0] = __expf(s[i][0] - mn); rs += s[i][0];
      s[i][1] = __expf(s[i][1] - mn); rs += s[i][1];
      s[i][2] = __expf(s[i][2] - mn); rs += s[i][2];
      s[i][3] = __expf(s[i][3] - mn); rs += s[i][3];
      rs += __shfl_xor_sync(0xffffffffu, rs, 1, 16);
      rs += __shfl_xor_sync(0xffffffffu, rs, 2, 16);
      rs += __shfl_xor_sync(0xffffffffu, rs, 4, 16);
      rs += __shfl_xor_sync(0xffffffffu, rs, 8, 16);

      lsum[i] = lsum[i] * f + rs;
      o[i][0] *= f;
      o[i][1] *= f;
      o[i][2] *= f;
      o[i][3] *= f;
    }

    __syncthreads();  // all Kt reads done before P overwrite
#pragma unroll
    for (int i = 0; i < 8; i++) {
      *(float4*)&KP[(ty * 8 + i) * PP + tx * 4] =
          make_float4(s[i][0], s[i][1], s[i][2], s[i][3]);
    }
    __syncthreads();

    // PV: o[i][j] += sum_k P[ty*8+i][k] * V[k][tx*4+j]
#pragma unroll 8
    for (int k = 0; k < KT; k++) {
      float4 vf = *(const float4*)&Vs[k * PVP + tx * 4];
#pragma unroll
      for (int i = 0; i < 8; i++) {
        float pv = KP[(ty * 8 + i) * PP + k];
        o[i][0] += pv * vf.x;
        o[i][1] += pv * vf.y;
        o[i][2] += pv * vf.z;
        o[i][3] += pv * vf.w;
      }
    }
  }

  // normalize + store merged-head output [B,S,D]
#pragma unroll
  for (int i = 0; i < 8; i++) {
    float inv = 1.f / lsum[i];
    float4 r = make_float4(o[i][0] * inv, o[i][1] * inv, o[i][2] * inv,
                           o[i][3] * inv);
    *(float4*)(Out + base + (size_t)(q0 + ty * 8 + i) * DM_ + tx * 4) = r;
  }
}

// ---------------- launch ----------------
extern "C" void kernel_launch(void* const* d_in, const int* in_sizes, int n_in,
                              void* d_out, int out_size) {
  const float* q_in = (const float*)d_in[0];
  const float* k_in = (const float*)d_in[1];
  const float* v_in = (const float*)d_in[2];
  const float* m_in = (const float*)d_in[3];
  const float* Wq = (const float*)d_in[4];
  const float* bq = (const float*)d_in[5];
  const float* Wk = (const float*)d_in[6];
  const float* bk = (const float*)d_in[7];
  const float* Wv = (const float*)d_in[8];
  const float* bv = (const float*)d_in[9];
  const float* Wo = (const float*)d_in[10];
  const float* bo = (const float*)d_in[11];
  float* out = (float*)d_out;

  float *Qp, *Kp, *Vp, *Ap;
  cudaGetSymbolAddress((void**)&Qp, g_Q);
  cudaGetSymbolAddress((void**)&Kp, g_K);
  cudaGetSymbolAddress((void**)&Vp, g_V);
  cudaGetSymbolAddress((void**)&Ap, g_attn);

  dim3 gb(DM_ / BN, (B_ * S_) / BM);
  gemm_bias_kernel<<<gb, 256>>>(q_in, Wq, bq, Qp);
  gemm_bias_kernel<<<gb, 256>>>(k_in, Wk, bk, Kp);
  gemm_bias_kernel<<<gb, 256>>>(v_in, Wv, bv, Vp);

  cudaFuncSetAttribute(attn_kernel, cudaFuncAttributeMaxDynamicSharedMemorySize,
                       ATTN_SMEM_BYTES);
  dim3 ga(S_ / QT, H_, B_);
  attn_kernel<<<ga, 256, ATTN_SMEM_BYTES>>>(Qp, Kp, Vp, m_in, Ap);

  gemm_bias_kernel<<<gb, 256>>>(Ap, Wo, bo, out);
}

// round 6
// speedup vs baseline: 1.2776x; 1.2776x over previous
#include <cuda_runtime.h>
#include <math.h>
#include <stdint.h>

#define B_ 4
#define S_ 2048
#define DM_ 1024
#define H_ 16
#define DEPTH_ 64

// ---------------- scratch (device globals; no allocation) ----------------
__device__ float g_Q[(size_t)B_ * S_ * DM_];
__device__ float g_K[(size_t)B_ * S_ * DM_];
__device__ float g_V[(size_t)B_ * S_ * DM_];
__device__ float g_attn[(size_t)B_ * S_ * DM_];

// ---------------- tf32 helpers ----------------
__device__ __forceinline__ float cvt_tf32(float x) {
  float r;
  asm("cvt.rna.tf32.f32 %0, %1;" : "=f"(r) : "f"(x));
  return r;
}

__device__ __forceinline__ void mma_tf32(float c[4], const unsigned a[4],
                                         const unsigned b[2]) {
  asm volatile(
      "mma.sync.aligned.m16n8k8.row.col.f32.tf32.tf32.f32 "
      "{%0,%1,%2,%3}, {%4,%5,%6,%7}, {%8,%9}, {%0,%1,%2,%3};"
      : "+f"(c[0]), "+f"(c[1]), "+f"(c[2]), "+f"(c[3])
      : "r"(a[0]), "r"(a[1]), "r"(a[2]), "r"(a[3]), "r"(b[0]), "r"(b[1]));
}

// ---------------- GEMM: C[M,N] = A[M,K] @ W[N,K]^T + bias  (tf32 tensor) ----
// M=8192, N=K=1024. CTA tile 128x128x32, 8 warps (2x4), warp tile 64x32.
#define GBM 128
#define GBN 128
#define GBK 32
#define GP 36                        // smem row pitch in floats ([m][k] tiles)
#define GSTAGE_F (GBM * GP)          // floats per stage per operand
#define GEMM_SMEM_BYTES (4 * GSTAGE_F * 4)  // 2 A stages + 2 W stages = 73728B

__global__ __launch_bounds__(256, 1) void gemm_tf32_kernel(
    const float* __restrict__ A, const float* __restrict__ W,
    const float* __restrict__ bias, float* __restrict__ C) {
  extern __shared__ float sm[];
  float* As = sm;                   // [2][GBM][GP]
  float* Ws = sm + 2 * GSTAGE_F;    // [2][GBN][GP]

  const int tid = threadIdx.x;
  const int lane = tid & 31;
  const int warp = tid >> 5;
  const int wm = (warp >> 2) * 64;  // warp row offset in CTA tile
  const int wn = (warp & 3) * 32;   // warp col offset
  const int g = lane >> 2;          // groupID 0..7
  const int tig = lane & 3;         // threadID_in_group 0..3
  const int rowBase = blockIdx.y * GBM;
  const int colBase = blockIdx.x * GBN;

  // global staging: each thread owns 4 float4 of A and 4 of W per k-tile
  const int lr = tid >> 3;          // 0..31 (+32*i)
  const int lc = (tid & 7) << 2;    // 0..28
  const float* Ag = A + (size_t)(rowBase + lr) * DM_ + lc;
  const float* Wg = W + (size_t)(colBase + lr) * DM_ + lc;

  float4 ra[4], rw[4];
#pragma unroll
  for (int i = 0; i < 4; i++) {
    ra[i] = *(const float4*)(Ag + (size_t)(32 * i) * DM_);
    rw[i] = *(const float4*)(Wg + (size_t)(32 * i) * DM_);
  }

  float acc[4][4][4];
#pragma unroll
  for (int mt = 0; mt < 4; mt++)
#pragma unroll
    for (int nt = 0; nt < 4; nt++)
#pragma unroll
      for (int e = 0; e < 4; e++) acc[mt][nt][e] = 0.f;

  // stage 0 store (tf32-rounded)
#pragma unroll
  for (int i = 0; i < 4; i++) {
    *(float4*)&As[(lr + 32 * i) * GP + lc] =
        make_float4(cvt_tf32(ra[i].x), cvt_tf32(ra[i].y), cvt_tf32(ra[i].z),
                    cvt_tf32(ra[i].w));
    *(float4*)&Ws[(lr + 32 * i) * GP + lc] =
        make_float4(cvt_tf32(rw[i].x), cvt_tf32(rw[i].y), cvt_tf32(rw[i].z),
                    cvt_tf32(rw[i].w));
  }
  __syncthreads();

  const int NT = DM_ / GBK;  // 32
  for (int kt = 0; kt < NT; kt++) {
    const int cur = kt & 1;
    if (kt + 1 < NT) {  // prefetch next k-tile into registers
      const int off = (kt + 1) * GBK;
#pragma unroll
      for (int i = 0; i < 4; i++) {
        ra[i] = *(const float4*)(Ag + (size_t)(32 * i) * DM_ + off);
        rw[i] = *(const float4*)(Wg + (size_t)(32 * i) * DM_ + off);
      }
    }
    const float* Ab = As + cur * GSTAGE_F;
    const float* Wb = Ws + cur * GSTAGE_F;
#pragma unroll
    for (int kk = 0; kk < 4; kk++) {
      const int k0 = kk * 8;
      unsigned af[4][4], bf[4][2];
#pragma unroll
      for (int mt = 0; mt < 4; mt++) {
        const float* p = Ab + (wm + mt * 16) * GP + k0;
        af[mt][0] = __float_as_uint(p[(g)*GP + tig]);
        af[mt][1] = __float_as_uint(p[(g + 8) * GP + tig]);
        af[mt][2] = __float_as_uint(p[(g)*GP + tig + 4]);
        af[mt][3] = __float_as_uint(p[(g + 8) * GP + tig + 4]);
      }
#pragma unroll
      for (int nt = 0; nt < 4; nt++) {
        const float* p = Wb + (wn + nt * 8 + g) * GP + k0;
        bf[nt][0] = __float_as_uint(p[tig]);
        bf[nt][1] = __float_as_uint(p[tig + 4]);
      }
#pragma unroll
      for (int mt = 0; mt < 4; mt++)
#pragma unroll
        for (int nt = 0; nt < 4; nt++) mma_tf32(acc[mt][nt], af[mt], bf[nt]);
    }
    if (kt + 1 < NT) {  // store staged regs into the other buffer
      float* Ad = As + (cur ^ 1) * GSTAGE_F;
      float* Wd = Ws + (cur ^ 1) * GSTAGE_F;
#pragma unroll
      for (int i = 0; i < 4; i++) {
        *(float4*)&Ad[(lr + 32 * i) * GP + lc] =
            make_float4(cvt_tf32(ra[i].x), cvt_tf32(ra[i].y), cvt_tf32(ra[i].z),
                        cvt_tf32(ra[i].w));
        *(float4*)&Wd[(lr + 32 * i) * GP + lc] =
            make_float4(cvt_tf32(rw[i].x), cvt_tf32(rw[i].y), cvt_tf32(rw[i].z),
                        cvt_tf32(rw[i].w));
      }
    }
    __syncthreads();
  }

  // epilogue: bias + store (fragment: rows g, g+8; cols 2*tig, 2*tig+1)
#pragma unroll
  for (int mt = 0; mt < 4; mt++) {
#pragma unroll
    for (int nt = 0; nt < 4; nt++) {
      const int r = rowBase + wm + mt * 16 + g;
      const int c = colBase + wn + nt * 8 + tig * 2;
      const float b0 = bias[c], b1 = bias[c + 1];
      *(float2*)(C + (size_t)r * DM_ + c) =
          make_float2(acc[mt][nt][0] + b0, acc[mt][nt][1] + b1);
      *(float2*)(C + (size_t)(r + 8) * DM_ + c) =
          make_float2(acc[mt][nt][2] + b0, acc[mt][nt][3] + b1);
    }
  }
}

// ---------------- fused masked-softmax attention (flash-style) ----------------
// One CTA per (b, h, 128-row q tile). 64-key tiles, online softmax.
#define QT 128
#define KT 64
#define PQ 68   // Qs pitch   [q][d]
#define PK 68   // Kt pitch   [d][key]   (transposed K for conflict-free f4 reads)
#define PP 68   // P pitch    [q][key]   (overlays Kt buffer)
#define PVP 68  // Vs pitch   [key][d]

#define ATTN_SMEM_FLOATS (QT * PQ + QT * PP + KT * PVP)
#define ATTN_SMEM_BYTES (ATTN_SMEM_FLOATS * 4)

__global__ __launch_bounds__(256, 2) void attn_kernel(
    const float* __restrict__ Q, const float* __restrict__ Kg,
    const float* __restrict__ Vg, const float* __restrict__ mask,
    float* __restrict__ Out) {
  extern __shared__ float sm[];
  float* Qs = sm;            // QT x PQ
  float* KP = sm + QT * PQ;  // Kt (KTxPK as [d][key]) then P (QTxPP)
  float* Vs = KP + QT * PP;  // KT x PVP

  int b = blockIdx.z, h = blockIdx.y;
  int q0 = blockIdx.x * QT;
  int tid = threadIdx.x, tx = tid & 15, ty = tid >> 4;
  size_t base = ((size_t)b * S_) * DM_ + (size_t)h * DEPTH_;

  // load Q tile [128 x 64]
  for (int l = tid; l < QT * 16; l += 256) {
    int r = l >> 4, c = (l & 15) * 4;
    *(float4*)&Qs[r * PQ + c] =
        *(const float4*)(Q + base + (size_t)(q0 + r) * DM_ + c);
  }

  float m[8], lsum[8], o[8][4];
#pragma unroll
  for (int i = 0; i < 8; i++) {
    m[i] = -1e30f;
    lsum[i] = 0.f;
    o[i][0] = o[i][1] = o[i][2] = o[i][3] = 0.f;
  }
  const float* maskBase = mask + (size_t)b * S_ * S_ + (size_t)q0 * S_;

  for (int kt = 0; kt < S_ / KT; kt++) {
    int k0 = kt * KT;
    __syncthreads();  // prev PV done reading KP(P)/Vs (also covers Qs on it 0)

    // load K tile transposed into KP as Kt[d][key]; V row-major
    for (int l = tid; l < KT * 16; l += 256) {
      int key = l >> 4, c = (l & 15) * 4;
      float4 kv = *(const float4*)(Kg + base + (size_t)(k0 + key) * DM_ + c);
      KP[(c + 0) * PK + key] = kv.x;
      KP[(c + 1) * PK + key] = kv.y;
      KP[(c + 2) * PK + key] = kv.z;
      KP[(c + 3) * PK + key] = kv.w;
      *(float4*)&Vs[key * PVP + c] =
          *(const float4*)(Vg + base + (size_t)(k0 + key) * DM_ + c);
    }
    __syncthreads();

    // scores: s[i][j] = Q[ty*8+i][:] . K[tx*4+j][:]  (4-d chunks, all f4 LDS)
    float s[8][4];
#pragma unroll
    for (int i = 0; i < 8; i++) s[i][0] = s[i][1] = s[i][2] = s[i][3] = 0.f;

#pragma unroll 2
    for (int d4 = 0; d4 < DEPTH_; d4 += 4) {
      const float* kp = &KP[d4 * PK + tx * 4];
      float4 k0f = *(const float4*)(kp);
      float4 k1f = *(const float4*)(kp + PK);
      float4 k2f = *(const float4*)(kp + 2 * PK);
      float4 k3f = *(const float4*)(kp + 3 * PK);
#pragma unroll
      for (int i = 0; i < 8; i++) {
        float4 qv = *(const float4*)&Qs[(ty * 8 + i) * PQ + d4];
        s[i][0] += qv.x * k0f.x + qv.y * k1f.x + qv.z * k2f.x + qv.w * k3f.x;
        s[i][1] += qv.x * k0f.y + qv.y * k1f.y + qv.z * k2f.y + qv.w * k3f.y;
        s[i][2] += qv.x * k0f.z + qv.y * k1f.z + qv.z * k2f.z + qv.w * k3f.z;
        s[i][3] += qv.x * k0f.w + qv.y * k1f.w + qv.z * k2f.w + qv.w * k3f.w;
      }
    }

    // mask + online softmax (row group = 16 lanes sharing ty → width-16 shfl)
#pragma unroll
    for (int i = 0; i < 8; i++) {
      float4 mm =
          *(const float4*)(maskBase + (size_t)(ty * 8 + i) * S_ + k0 + tx * 4);
      s[i][0] = s[i][0] * 0.125f - 1e6f * mm.x;
      s[i][1] = s[i][1] * 0.125f - 1e6f * mm.y;
      s[i][2] = s[i][2] * 0.125f - 1e6f * mm.z;
      s[i][3] = s[i][3] * 0.125f - 1e6f * mm.w;

      float mx = fmaxf(fmaxf(s[i][0], s[i][1]), fmaxf(s[i][2], s[i][3]));
      mx = fmaxf(mx, __shfl_xor_sync(0xffffffffu, mx, 1, 16));
      mx = fmaxf(mx, __shfl_xor_sync(0xffffffffu, mx, 2, 16));
      mx = fmaxf(mx, __shfl_xor_sync(0xffffffffu, mx, 4, 16));
      mx = fmaxf(mx, __shfl_xor_sync(0xffffffffu, mx, 8, 16));

      float mn = fmaxf(m[i], mx);
      float f = __expf(m[i] - mn);
      m[i] = mn;

      float rs = 0.f;
      s[i][0] = __expf(s[i][0] - mn); rs += s[i][0];
      s[i][1] = __expf(s[i][1] - mn); rs += s[i][1];
      s[i][2] = __expf(s[i][2] - mn); rs += s[i][2];
      s[i][3] = __expf(s[i][3] - mn); rs += s[i][3];
      rs += __shfl_xor_sync(0xffffffffu, rs, 1, 16);
      rs += __shfl_xor_sync(0xffffffffu, rs, 2, 16);
      rs += __shfl_xor_sync(0xffffffffu, rs, 4, 16);
      rs += __shfl_xor_sync(0xffffffffu, rs, 8, 16);

      lsum[i] = lsum[i] * f + rs;
      o[i][0] *= f;
      o[i][1] *= f;
      o[i][2] *= f;
      o[i][3] *= f;
    }

    __syncthreads();  // all Kt reads done before P overwrite
#pragma unroll
    for (int i = 0; i < 8; i++) {
      *(float4*)&KP[(ty * 8 + i) * PP + tx * 4] =
          make_float4(s[i][0], s[i][1], s[i][2], s[i][3]);
    }
    __syncthreads();

    // PV: o[i][j] += sum_k P[ty*8+i][k] * V[k][tx*4+j]  (4-k chunks, all f4)
#pragma unroll 2
    for (int k4 = 0; k4 < KT; k4 += 4) {
      const float* vp = &Vs[k4 * PVP + tx * 4];
      float4 v0 = *(const float4*)(vp);
      float4 v1 = *(const float4*)(vp + PVP);
      float4 v2 = *(const float4*)(vp + 2 * PVP);
      float4 v3 = *(const float4*)(vp + 3 * PVP);
#pragma unroll
      for (int i = 0; i < 8; i++) {
        float4 pv = *(const float4*)&KP[(ty * 8 + i) * PP + k4];
        o[i][0] += pv.x * v0.x + pv.y * v1.x + pv.z * v2.x + pv.w * v3.x;
        o[i][1] += pv.x * v0.y + pv.y * v1.y + pv.z * v2.y + pv.w * v3.y;
        o[i][2] += pv.x * v0.z + pv.y * v1.z + pv.z * v2.z + pv.w * v3.z;
        o[i][3] += pv.x * v0.w + pv.y * v1.w + pv.z * v2.w + pv.w * v3.w;
      }
    }
  }

  // normalize + store merged-head output [B,S,D]
#pragma unroll
  for (int i = 0; i < 8; i++) {
    float inv = 1.f / lsum[i];
    float4 r = make_float4(o[i][0] * inv, o[i][1] * inv, o[i][2] * inv,
                           o[i][3] * inv);
    *(float4*)(Out + base + (size_t)(q0 + ty * 8 + i) * DM_ + tx * 4) = r;
  }
}

// ---------------- launch ----------------
extern "C" void kernel_launch(void* const* d_in, const int* in_sizes, int n_in,
                              void* d_out, int out_size) {
  const float* q_in = (const float*)d_in[0];
  const float* k_in = (const float*)d_in[1];
  const float* v_in = (const float*)d_in[2];
  const float* m_in = (const float*)d_in[3];
  const float* Wq = (const float*)d_in[4];
  const float* bq = (const float*)d_in[5];
  const float* Wk = (const float*)d_in[6];
  const float* bk = (const float*)d_in[7];
  const float* Wv = (const float*)d_in[8];
  const float* bv = (const float*)d_in[9];
  const float* Wo = (const float*)d_in[10];
  const float* bo = (const float*)d_in[11];
  float* out = (float*)d_out;

  float *Qp, *Kp, *Vp, *Ap;
  cudaGetSymbolAddress((void**)&Qp, g_Q);
  cudaGetSymbolAddress((void**)&Kp, g_K);
  cudaGetSymbolAddress((void**)&Vp, g_V);
  cudaGetSymbolAddress((void**)&Ap, g_attn);

  cudaFuncSetAttribute(gemm_tf32_kernel,
                       cudaFuncAttributeMaxDynamicSharedMemorySize,
                       GEMM_SMEM_BYTES);
  cudaFuncSetAttribute(attn_kernel, cudaFuncAttributeMaxDynamicSharedMemorySize,
                       ATTN_SMEM_BYTES);

  dim3 gb(DM_ / GBN, (B_ * S_) / GBM);
  gemm_tf32_kernel<<<gb, 256, GEMM_SMEM_BYTES>>>(q_in, Wq, bq, Qp);
  gemm_tf32_kernel<<<gb, 256, GEMM_SMEM_BYTES>>>(k_in, Wk, bk, Kp);
  gemm_tf32_kernel<<<gb, 256, GEMM_SMEM_BYTES>>>(v_in, Wv, bv, Vp);

  dim3 ga(S_ / QT, H_, B_);
  attn_kernel<<<ga, 256, ATTN_SMEM_BYTES>>>(Qp, Kp, Vp, m_in, Ap);

  gemm_tf32_kernel<<<gb, 256, GEMM_SMEM_BYTES>>>(Ap, Wo, bo, out);
}

// round 7
// speedup vs baseline: 1.2784x; 1.0006x over previous
#include <cuda_runtime.h>
#include <math.h>
#include <stdint.h>

#define B_ 4
#define S_ 2048
#define DM_ 1024
#define H_ 16
#define DEPTH_ 64

// ---------------- scratch (device globals; no allocation) ----------------
__device__ float g_Q[(size_t)B_ * S_ * DM_];
__device__ float g_K[(size_t)B_ * S_ * DM_];
__device__ float g_V[(size_t)B_ * S_ * DM_];
__device__ float g_attn[(size_t)B_ * S_ * DM_];

// ---------------- tf32 helpers ----------------
__device__ __forceinline__ float cvt_tf32(float x) {
  float r;
  asm("cvt.rna.tf32.f32 %0, %1;" : "=f"(r) : "f"(x));
  return r;
}

__device__ __forceinline__ void mma_tf32(float c[4], const unsigned a[4],
                                         const unsigned b[2]) {
  asm volatile(
      "mma.sync.aligned.m16n8k8.row.col.f32.tf32.tf32.f32 "
      "{%0,%1,%2,%3}, {%4,%5,%6,%7}, {%8,%9}, {%0,%1,%2,%3};"
      : "+f"(c[0]), "+f"(c[1]), "+f"(c[2]), "+f"(c[3])
      : "r"(a[0]), "r"(a[1]), "r"(a[2]), "r"(a[3]), "r"(b[0]), "r"(b[1]));
}

// ---------------- GEMM: C[M,N] = A[M,K] @ W[N,K]^T + bias  (tf32 tensor) ----
// M=8192, N=K=1024. CTA tile 128x128x32, 8 warps (2x4), warp tile 64x32.
#define GBM 128
#define GBN 128
#define GBK 32
#define GP 36                        // smem row pitch in floats ([m][k] tiles)
#define GSTAGE_F (GBM * GP)          // floats per stage per operand
#define GEMM_SMEM_BYTES (4 * GSTAGE_F * 4)  // 2 A stages + 2 W stages = 73728B

__global__ __launch_bounds__(256, 1) void gemm_tf32_kernel(
    const float* __restrict__ A, const float* __restrict__ W,
    const float* __restrict__ bias, float* __restrict__ C) {
  extern __shared__ float sm[];
  float* As = sm;                   // [2][GBM][GP]
  float* Ws = sm + 2 * GSTAGE_F;    // [2][GBN][GP]

  const int tid = threadIdx.x;
  const int lane = tid & 31;
  const int warp = tid >> 5;
  const int wm = (warp >> 2) * 64;  // warp row offset in CTA tile
  const int wn = (warp & 3) * 32;   // warp col offset
  const int g = lane >> 2;          // groupID 0..7
  const int tig = lane & 3;         // threadID_in_group 0..3
  const int rowBase = blockIdx.y * GBM;
  const int colBase = blockIdx.x * GBN;

  // global staging: each thread owns 4 float4 of A and 4 of W per k-tile
  const int lr = tid >> 3;          // 0..31 (+32*i)
  const int lc = (tid & 7) << 2;    // 0..28
  const float* Ag = A + (size_t)(rowBase + lr) * DM_ + lc;
  const float* Wg = W + (size_t)(colBase + lr) * DM_ + lc;

  float4 ra[4], rw[4];
#pragma unroll
  for (int i = 0; i < 4; i++) {
    ra[i] = *(const float4*)(Ag + (size_t)(32 * i) * DM_);
    rw[i] = *(const float4*)(Wg + (size_t)(32 * i) * DM_);
  }

  float acc[4][4][4];
#pragma unroll
  for (int mt = 0; mt < 4; mt++)
#pragma unroll
    for (int nt = 0; nt < 4; nt++)
#pragma unroll
      for (int e = 0; e < 4; e++) acc[mt][nt][e] = 0.f;

  // stage 0 store (tf32-rounded)
#pragma unroll
  for (int i = 0; i < 4; i++) {
    *(float4*)&As[(lr + 32 * i) * GP + lc] =
        make_float4(cvt_tf32(ra[i].x), cvt_tf32(ra[i].y), cvt_tf32(ra[i].z),
                    cvt_tf32(ra[i].w));
    *(float4*)&Ws[(lr + 32 * i) * GP + lc] =
        make_float4(cvt_tf32(rw[i].x), cvt_tf32(rw[i].y), cvt_tf32(rw[i].z),
                    cvt_tf32(rw[i].w));
  }
  __syncthreads();

  const int NT = DM_ / GBK;  // 32
  for (int kt = 0; kt < NT; kt++) {
    const int cur = kt & 1;
    if (kt + 1 < NT) {  // prefetch next k-tile into registers
      const int off = (kt + 1) * GBK;
#pragma unroll
      for (int i = 0; i < 4; i++) {
        ra[i] = *(const float4*)(Ag + (size_t)(32 * i) * DM_ + off);
        rw[i] = *(const float4*)(Wg + (size_t)(32 * i) * DM_ + off);
      }
    }
    const float* Ab = As + cur * GSTAGE_F;
    const float* Wb = Ws + cur * GSTAGE_F;
#pragma unroll
    for (int kk = 0; kk < 4; kk++) {
      const int k0 = kk * 8;
      unsigned af[4][4], bf[4][2];
#pragma unroll
      for (int mt = 0; mt < 4; mt++) {
        const float* p = Ab + (wm + mt * 16) * GP + k0;
        af[mt][0] = __float_as_uint(p[(g)*GP + tig]);
        af[mt][1] = __float_as_uint(p[(g + 8) * GP + tig]);
        af[mt][2] = __float_as_uint(p[(g)*GP + tig + 4]);
        af[mt][3] = __float_as_uint(p[(g + 8) * GP + tig + 4]);
      }
#pragma unroll
      for (int nt = 0; nt < 4; nt++) {
        const float* p = Wb + (wn + nt * 8 + g) * GP + k0;
        bf[nt][0] = __float_as_uint(p[tig]);
        bf[nt][1] = __float_as_uint(p[tig + 4]);
      }
#pragma unroll
      for (int mt = 0; mt < 4; mt++)
#pragma unroll
        for (int nt = 0; nt < 4; nt++) mma_tf32(acc[mt][nt], af[mt], bf[nt]);
    }
    if (kt + 1 < NT) {  // store staged regs into the other buffer
      float* Ad = As + (cur ^ 1) * GSTAGE_F;
      float* Wd = Ws + (cur ^ 1) * GSTAGE_F;
#pragma unroll
      for (int i = 0; i < 4; i++) {
        *(float4*)&Ad[(lr + 32 * i) * GP + lc] =
            make_float4(cvt_tf32(ra[i].x), cvt_tf32(ra[i].y), cvt_tf32(ra[i].z),
                        cvt_tf32(ra[i].w));
        *(float4*)&Wd[(lr + 32 * i) * GP + lc] =
            make_float4(cvt_tf32(rw[i].x), cvt_tf32(rw[i].y), cvt_tf32(rw[i].z),
                        cvt_tf32(rw[i].w));
      }
    }
    __syncthreads();
  }

  // epilogue: bias + store (fragment: rows g, g+8; cols 2*tig, 2*tig+1)
#pragma unroll
  for (int mt = 0; mt < 4; mt++) {
#pragma unroll
    for (int nt = 0; nt < 4; nt++) {
      const int r = rowBase + wm + mt * 16 + g;
      const int c = colBase + wn + nt * 8 + tig * 2;
      const float b0 = bias[c], b1 = bias[c + 1];
      *(float2*)(C + (size_t)r * DM_ + c) =
          make_float2(acc[mt][nt][0] + b0, acc[mt][nt][1] + b1);
      *(float2*)(C + (size_t)(r + 8) * DM_ + c) =
          make_float2(acc[mt][nt][2] + b0, acc[mt][nt][3] + b1);
    }
  }
}

// ---------------- fused masked-softmax attention (flash-style) ----------------
// One CTA per (b, h, 128-row q tile). 64-key tiles, online softmax.
#define QT 128
#define KT 64
#define PQ 68   // Qs pitch   [q][d]
#define PK 68   // Kt pitch   [d][key]   (transposed K for conflict-free f4 reads)
#define PP 68   // P pitch    [q][key]   (overlays Kt buffer)
#define PVP 68  // Vs pitch   [key][d]

#define ATTN_SMEM_FLOATS (QT * PQ + QT * PP + KT * PVP)
#define ATTN_SMEM_BYTES (ATTN_SMEM_FLOATS * 4)

__global__ __launch_bounds__(256, 2) void attn_kernel(
    const float* __restrict__ Q, const float* __restrict__ Kg,
    const float* __restrict__ Vg, const float* __restrict__ mask,
    float* __restrict__ Out) {
  extern __shared__ float sm[];
  float* Qs = sm;            // QT x PQ
  float* KP = sm + QT * PQ;  // Kt (KTxPK as [d][key]) then P (QTxPP)
  float* Vs = KP + QT * PP;  // KT x PVP

  int b = blockIdx.z, h = blockIdx.y;
  int q0 = blockIdx.x * QT;
  int tid = threadIdx.x, tx = tid & 15, ty = tid >> 4;
  size_t base = ((size_t)b * S_) * DM_ + (size_t)h * DEPTH_;

  // load Q tile [128 x 64]
  for (int l = tid; l < QT * 16; l += 256) {
    int r = l >> 4, c = (l & 15) * 4;
    *(float4*)&Qs[r * PQ + c] =
        *(const float4*)(Q + base + (size_t)(q0 + r) * DM_ + c);
  }

  float m[8], lsum[8], o[8][4];
#pragma unroll
  for (int i = 0; i < 8; i++) {
    m[i] = -1e30f;
    lsum[i] = 0.f;
    o[i][0] = o[i][1] = o[i][2] = o[i][3] = 0.f;
  }
  const float* maskBase = mask + (size_t)b * S_ * S_ + (size_t)q0 * S_;

  for (int kt = 0; kt < S_ / KT; kt++) {
    int k0 = kt * KT;
    __syncthreads();  // prev PV done reading KP(P)/Vs (also covers Qs on it 0)

    // load K tile transposed into KP as Kt[d][key]; V row-major
    for (int l = tid; l < KT * 16; l += 256) {
      int key = l >> 4, c = (l & 15) * 4;
      float4 kv = *(const float4*)(Kg + base + (size_t)(k0 + key) * DM_ + c);
      KP[(c + 0) * PK + key] = kv.x;
      KP[(c + 1) * PK + key] = kv.y;
      KP[(c + 2) * PK + key] = kv.z;
      KP[(c + 3) * PK + key] = kv.w;
      *(float4*)&Vs[key * PVP + c] =
          *(const float4*)(Vg + base + (size_t)(k0 + key) * DM_ + c);
    }
    __syncthreads();

    // scores: s[i][j] = Q[ty*8+i][:] . K[tx*4+j][:]  (4-d chunks, all f4 LDS)
    float s[8][4];
#pragma unroll
    for (int i = 0; i < 8; i++) s[i][0] = s[i][1] = s[i][2] = s[i][3] = 0.f;

#pragma unroll 2
    for (int d4 = 0; d4 < DEPTH_; d4 += 4) {
      const float* kp = &KP[d4 * PK + tx * 4];
      float4 k0f = *(const float4*)(kp);
      float4 k1f = *(const float4*)(kp + PK);
      float4 k2f = *(const float4*)(kp + 2 * PK);
      float4 k3f = *(const float4*)(kp + 3 * PK);
#pragma unroll
      for (int i = 0; i < 8; i++) {
        float4 qv = *(const float4*)&Qs[(ty * 8 + i) * PQ + d4];
        s[i][0] += qv.x * k0f.x + qv.y * k1f.x + qv.z * k2f.x + qv.w * k3f.x;
        s[i][1] += qv.x * k0f.y + qv.y * k1f.y + qv.z * k2f.y + qv.w * k3f.y;
        s[i][2] += qv.x * k0f.z + qv.y * k1f.z + qv.z * k2f.z + qv.w * k3f.z;
        s[i][3] += qv.x * k0f.w + qv.y * k1f.w + qv.z * k2f.w + qv.w * k3f.w;
      }
    }

    // mask + online softmax (row group = 16 lanes sharing ty → width-16 shfl)
#pragma unroll
    for (int i = 0; i < 8; i++) {
      float4 mm =
          *(const float4*)(maskBase + (size_t)(ty * 8 + i) * S_ + k0 + tx * 4);
      s[i][0] = s[i][0] * 0.125f - 1e6f * mm.x;
      s[i][1] = s[i][1] * 0.125f - 1e6f * mm.y;
      s[i][2] = s[i][2] * 0.125f - 1e6f * mm.z;
      s[i][3] = s[i][3] * 0.125f - 1e6f * mm.w;

      float mx = fmaxf(fmaxf(s[i][0], s[i][1]), fmaxf(s[i][2], s[i][3]));
      mx = fmaxf(mx, __shfl_xor_sync(0xffffffffu, mx, 1, 16));
      mx = fmaxf(mx, __shfl_xor_sync(0xffffffffu, mx, 2, 16));
      mx = fmaxf(mx, __shfl_xor_sync(0xffffffffu, mx, 4, 16));
      mx = fmaxf(mx, __shfl_xor_sync(0xffffffffu, mx, 8, 16));

      float mn = fmaxf(m[i], mx);
      float f = __expf(m[i] - mn);
      m[i] = mn;

      float rs = 0.f;
      s[i][0] = __expf(s[i][0] - mn); rs += s[i][0];
      s[i][1] = __expf(s[i][1] - mn); rs += s[i][1];
      s[i][2] = __expf(s[i][2] - mn); rs += s[i][2];
      s[i][3] = __expf(s[i][3] - mn); rs += s[i][3];
      rs += __shfl_xor_sync(0xffffffffu, rs, 1, 16);
      rs += __shfl_xor_sync(0xffffffffu, rs, 2, 16);
      rs += __shfl_xor_sync(0xffffffffu, rs, 4, 16);
      rs += __shfl_xor_sync(0xffffffffu, rs, 8, 16);

      lsum[i] = lsum[i] * f + rs;
      o[i][0] *= f;
      o[i][1] *= f;
      o[i][2] *= f;
      o[i][3] *= f;
    }

    __syncthreads();  // all Kt reads done before P overwrite
#pragma unroll
    for (int i = 0; i < 8; i++) {
      *(float4*)&KP[(ty * 8 + i) * PP + tx * 4] =
          make_float4(s[i][0], s[i][1], s[i][2], s[i][3]);
    }
    __syncthreads();

    // PV: o[i][j] += sum_k P[ty*8+i][k] * V[k][tx*4+j]  (4-k chunks, all f4)
#pragma unroll 2
    for (int k4 = 0; k4 < KT; k4 += 4) {
      const float* vp = &Vs[k4 * PVP + tx * 4];
      float4 v0 = *(const float4*)(vp);
      float4 v1 = *(const float4*)(vp + PVP);
      float4 v2 = *(const float4*)(vp + 2 * PVP);
      float4 v3 = *(const float4*)(vp + 3 * PVP);
#pragma unroll
      for (int i = 0; i < 8; i++) {
        float4 pv = *(const float4*)&KP[(ty * 8 + i) * PP + k4];
        o[i][0] += pv.x * v0.x + pv.y * v1.x + pv.z * v2.x + pv.w * v3.x;
        o[i][1] += pv.x * v0.y + pv.y * v1.y + pv.z * v2.y + pv.w * v3.y;
        o[i][2] += pv.x * v0.z + pv.y * v1.z + pv.z * v2.z + pv.w * v3.z;
        o[i][3] += pv.x * v0.w + pv.y * v1.w + pv.z * v2.w + pv.w * v3.w;
      }
    }
  }

  // normalize + store merged-head output [B,S,D]
#pragma unroll
  for (int i = 0; i < 8; i++) {
    float inv = 1.f / lsum[i];
    float4 r = make_float4(o[i][0] * inv, o[i][1] * inv, o[i][2] * inv,
                           o[i][3] * inv);
    *(float4*)(Out + base + (size_t)(q0 + ty * 8 + i) * DM_ + tx * 4) = r;
  }
}

// ---------------- launch ----------------
extern "C" void kernel_launch(void* const* d_in, const int* in_sizes, int n_in,
                              void* d_out, int out_size) {
  const float* q_in = (const float*)d_in[0];
  const float* k_in = (const float*)d_in[1];
  const float* v_in = (const float*)d_in[2];
  const float* m_in = (const float*)d_in[3];
  const float* Wq = (const float*)d_in[4];
  const float* bq = (const float*)d_in[5];
  const float* Wk = (const float*)d_in[6];
  const float* bk = (const float*)d_in[7];
  const float* Wv = (const float*)d_in[8];
  const float* bv = (const float*)d_in[9];
  const float* Wo = (const float*)d_in[10];
  const float* bo = (const float*)d_in[11];
  float* out = (float*)d_out;

  float *Qp, *Kp, *Vp, *Ap;
  cudaGetSymbolAddress((void**)&Qp, g_Q);
  cudaGetSymbolAddress((void**)&Kp, g_K);
  cudaGetSymbolAddress((void**)&Vp, g_V);
  cudaGetSymbolAddress((void**)&Ap, g_attn);

  cudaFuncSetAttribute(gemm_tf32_kernel,
                       cudaFuncAttributeMaxDynamicSharedMemorySize,
                       GEMM_SMEM_BYTES);
  cudaFuncSetAttribute(attn_kernel, cudaFuncAttributeMaxDynamicSharedMemorySize,
                       ATTN_SMEM_BYTES);

  dim3 gb(DM_ / GBN, (B_ * S_) / GBM);
  gemm_tf32_kernel<<<gb, 256, GEMM_SMEM_BYTES>>>(q_in, Wq, bq, Qp);
  gemm_tf32_kernel<<<gb, 256, GEMM_SMEM_BYTES>>>(k_in, Wk, bk, Kp);
  gemm_tf32_kernel<<<gb, 256, GEMM_SMEM_BYTES>>>(v_in, Wv, bv, Vp);

  dim3 ga(S_ / QT, H_, B_);
  attn_kernel<<<ga, 256, ATTN_SMEM_BYTES>>>(Qp, Kp, Vp, m_in, Ap);

  gemm_tf32_kernel<<<gb, 256, GEMM_SMEM_BYTES>>>(Ap, Wo, bo, out);
}

// round 8
// speedup vs baseline: 1.2790x; 1.0005x over previous
#include <cuda_runtime.h>
#include <math.h>
#include <stdint.h>

#define B_ 4
#define S_ 2048
#define DM_ 1024
#define H_ 16
#define DEPTH_ 64

// ---------------- scratch (device globals; no allocation) ----------------
__device__ float g_Q[(size_t)B_ * S_ * DM_];
__device__ float g_K[(size_t)B_ * S_ * DM_];
__device__ float g_V[(size_t)B_ * S_ * DM_];
__device__ float g_attn[(size_t)B_ * S_ * DM_];

// ---------------- tf32 helpers ----------------
__device__ __forceinline__ float cvt_tf32(float x) {
  float r;
  asm("cvt.rna.tf32.f32 %0, %1;" : "=f"(r) : "f"(x));
  return r;
}

__device__ __forceinline__ void mma_tf32(float c[4], const unsigned a[4],
                                         const unsigned b[2]) {
  asm volatile(
      "mma.sync.aligned.m16n8k8.row.col.f32.tf32.tf32.f32 "
      "{%0,%1,%2,%3}, {%4,%5,%6,%7}, {%8,%9}, {%0,%1,%2,%3};"
      : "+f"(c[0]), "+f"(c[1]), "+f"(c[2]), "+f"(c[3])
      : "r"(a[0]), "r"(a[1]), "r"(a[2]), "r"(a[3]), "r"(b[0]), "r"(b[1]));
}

// ---------------- GEMM: C[M,N] = A[M,K] @ W[N,K]^T + bias  (tf32 tensor) ----
// M=8192, N=K=1024. CTA tile 128x128x32, 8 warps (2x4), warp tile 64x32.
#define GBM 128
#define GBN 128
#define GBK 32
#define GP 36                        // smem row pitch in floats ([m][k] tiles)
#define GSTAGE_F (GBM * GP)          // floats per stage per operand
#define GEMM_SMEM_BYTES (4 * GSTAGE_F * 4)  // 2 A stages + 2 W stages = 73728B

__global__ __launch_bounds__(256, 1) void gemm_tf32_kernel(
    const float* __restrict__ A, const float* __restrict__ W,
    const float* __restrict__ bias, float* __restrict__ C) {
  extern __shared__ float sm[];
  float* As = sm;                   // [2][GBM][GP]
  float* Ws = sm + 2 * GSTAGE_F;    // [2][GBN][GP]

  const int tid = threadIdx.x;
  const int lane = tid & 31;
  const int warp = tid >> 5;
  const int wm = (warp >> 2) * 64;  // warp row offset in CTA tile
  const int wn = (warp & 3) * 32;   // warp col offset
  const int g = lane >> 2;          // groupID 0..7
  const int tig = lane & 3;         // threadID_in_group 0..3
  const int rowBase = blockIdx.y * GBM;
  const int colBase = blockIdx.x * GBN;

  // global staging: each thread owns 4 float4 of A and 4 of W per k-tile
  const int lr = tid >> 3;          // 0..31 (+32*i)
  const int lc = (tid & 7) << 2;    // 0..28
  const float* Ag = A + (size_t)(rowBase + lr) * DM_ + lc;
  const float* Wg = W + (size_t)(colBase + lr) * DM_ + lc;

  float4 ra[4], rw[4];
#pragma unroll
  for (int i = 0; i < 4; i++) {
    ra[i] = *(const float4*)(Ag + (size_t)(32 * i) * DM_);
    rw[i] = *(const float4*)(Wg + (size_t)(32 * i) * DM_);
  }

  float acc[4][4][4];
#pragma unroll
  for (int mt = 0; mt < 4; mt++)
#pragma unroll
    for (int nt = 0; nt < 4; nt++)
#pragma unroll
      for (int e = 0; e < 4; e++) acc[mt][nt][e] = 0.f;

  // stage 0 store (tf32-rounded)
#pragma unroll
  for (int i = 0; i < 4; i++) {
    *(float4*)&As[(lr + 32 * i) * GP + lc] =
        make_float4(cvt_tf32(ra[i].x), cvt_tf32(ra[i].y), cvt_tf32(ra[i].z),
                    cvt_tf32(ra[i].w));
    *(float4*)&Ws[(lr + 32 * i) * GP + lc] =
        make_float4(cvt_tf32(rw[i].x), cvt_tf32(rw[i].y), cvt_tf32(rw[i].z),
                    cvt_tf32(rw[i].w));
  }
  __syncthreads();

  const int NT = DM_ / GBK;  // 32
  for (int kt = 0; kt < NT; kt++) {
    const int cur = kt & 1;
    if (kt + 1 < NT) {  // prefetch next k-tile into registers
      const int off = (kt + 1) * GBK;
#pragma unroll
      for (int i = 0; i < 4; i++) {
        ra[i] = *(const float4*)(Ag + (size_t)(32 * i) * DM_ + off);
        rw[i] = *(const float4*)(Wg + (size_t)(32 * i) * DM_ + off);
      }
    }
    const float* Ab = As + cur * GSTAGE_F;
    const float* Wb = Ws + cur * GSTAGE_F;
#pragma unroll
    for (int kk = 0; kk < 4; kk++) {
      const int k0 = kk * 8;
      unsigned af[4][4], bf[4][2];
#pragma unroll
      for (int mt = 0; mt < 4; mt++) {
        const float* p = Ab + (wm + mt * 16) * GP + k0;
        af[mt][0] = __float_as_uint(p[(g)*GP + tig]);
        af[mt][1] = __float_as_uint(p[(g + 8) * GP + tig]);
        af[mt][2] = __float_as_uint(p[(g)*GP + tig + 4]);
        af[mt][3] = __float_as_uint(p[(g + 8) * GP + tig + 4]);
      }
#pragma unroll
      for (int nt = 0; nt < 4; nt++) {
        const float* p = Wb + (wn + nt * 8 + g) * GP + k0;
        bf[nt][0] = __float_as_uint(p[tig]);
        bf[nt][1] = __float_as_uint(p[tig + 4]);
      }
#pragma unroll
      for (int mt = 0; mt < 4; mt++)
#pragma unroll
        for (int nt = 0; nt < 4; nt++) mma_tf32(acc[mt][nt], af[mt], bf[nt]);
    }
    if (kt + 1 < NT) {  // store staged regs into the other buffer
      float* Ad = As + (cur ^ 1) * GSTAGE_F;
      float* Wd = Ws + (cur ^ 1) * GSTAGE_F;
#pragma unroll
      for (int i = 0; i < 4; i++) {
        *(float4*)&Ad[(lr + 32 * i) * GP + lc] =
            make_float4(cvt_tf32(ra[i].x), cvt_tf32(ra[i].y), cvt_tf32(ra[i].z),
                        cvt_tf32(ra[i].w));
        *(float4*)&Wd[(lr + 32 * i) * GP + lc] =
            make_float4(cvt_tf32(rw[i].x), cvt_tf32(rw[i].y), cvt_tf32(rw[i].z),
                        cvt_tf32(rw[i].w));
      }
    }
    __syncthreads();
  }

  // epilogue: bias + store (fragment: rows g, g+8; cols 2*tig, 2*tig+1)
#pragma unroll
  for (int mt = 0; mt < 4; mt++) {
#pragma unroll
    for (int nt = 0; nt < 4; nt++) {
      const int r = rowBase + wm + mt * 16 + g;
      const int c = colBase + wn + nt * 8 + tig * 2;
      const float b0 = bias[c], b1 = bias[c + 1];
      *(float2*)(C + (size_t)r * DM_ + c) =
          make_float2(acc[mt][nt][0] + b0, acc[mt][nt][1] + b1);
      *(float2*)(C + (size_t)(r + 8) * DM_ + c) =
          make_float2(acc[mt][nt][2] + b0, acc[mt][nt][3] + b1);
    }
  }
}

// ---------------- fused masked-softmax attention (flash-style) ----------------
// One CTA per (b, h, 128-row q tile). 64-key tiles, online softmax.
#define QT 128
#define KT 64
#define PQ 68   // Qs pitch   [q][d]
#define PK 68   // Kt pitch   [d][key]   (transposed K for conflict-free f4 reads)
#define PP 68   // P pitch    [q][key]   (overlays Kt buffer)
#define PVP 68  // Vs pitch   [key][d]

#define ATTN_SMEM_FLOATS (QT * PQ + QT * PP + KT * PVP)
#define ATTN_SMEM_BYTES (ATTN_SMEM_FLOATS * 4)

__global__ __launch_bounds__(256, 2) void attn_kernel(
    const float* __restrict__ Q, const float* __restrict__ Kg,
    const float* __restrict__ Vg, const float* __restrict__ mask,
    float* __restrict__ Out) {
  extern __shared__ float sm[];
  float* Qs = sm;            // QT x PQ
  float* KP = sm + QT * PQ;  // Kt (KTxPK as [d][key]) then P (QTxPP)
  float* Vs = KP + QT * PP;  // KT x PVP

  int b = blockIdx.z, h = blockIdx.y;
  int q0 = blockIdx.x * QT;
  int tid = threadIdx.x, tx = tid & 15, ty = tid >> 4;
  size_t base = ((size_t)b * S_) * DM_ + (size_t)h * DEPTH_;

  // load Q tile [128 x 64]
  for (int l = tid; l < QT * 16; l += 256) {
    int r = l >> 4, c = (l & 15) * 4;
    *(float4*)&Qs[r * PQ + c] =
        *(const float4*)(Q + base + (size_t)(q0 + r) * DM_ + c);
  }

  float m[8], lsum[8], o[8][4];
#pragma unroll
  for (int i = 0; i < 8; i++) {
    m[i] = -1e30f;
    lsum[i] = 0.f;
    o[i][0] = o[i][1] = o[i][2] = o[i][3] = 0.f;
  }
  const float* maskBase = mask + (size_t)b * S_ * S_ + (size_t)q0 * S_;

  for (int kt = 0; kt < S_ / KT; kt++) {
    int k0 = kt * KT;
    __syncthreads();  // prev PV done reading KP(P)/Vs (also covers Qs on it 0)

    // load K tile transposed into KP as Kt[d][key]; V row-major
    for (int l = tid; l < KT * 16; l += 256) {
      int key = l >> 4, c = (l & 15) * 4;
      float4 kv = *(const float4*)(Kg + base + (size_t)(k0 + key) * DM_ + c);
      KP[(c + 0) * PK + key] = kv.x;
      KP[(c + 1) * PK + key] = kv.y;
      KP[(c + 2) * PK + key] = kv.z;
      KP[(c + 3) * PK + key] = kv.w;
      *(float4*)&Vs[key * PVP + c] =
          *(const float4*)(Vg + base + (size_t)(k0 + key) * DM_ + c);
    }
    __syncthreads();

    // scores: s[i][j] = Q[ty*8+i][:] . K[tx*4+j][:]  (4-d chunks, all f4 LDS)
    float s[8][4];
#pragma unroll
    for (int i = 0; i < 8; i++) s[i][0] = s[i][1] = s[i][2] = s[i][3] = 0.f;

#pragma unroll 2
    for (int d4 = 0; d4 < DEPTH_; d4 += 4) {
      const float* kp = &KP[d4 * PK + tx * 4];
      float4 k0f = *(const float4*)(kp);
      float4 k1f = *(const float4*)(kp + PK);
      float4 k2f = *(const float4*)(kp + 2 * PK);
      float4 k3f = *(const float4*)(kp + 3 * PK);
#pragma unroll
      for (int i = 0; i < 8; i++) {
        float4 qv = *(const float4*)&Qs[(ty * 8 + i) * PQ + d4];
        s[i][0] += qv.x * k0f.x + qv.y * k1f.x + qv.z * k2f.x + qv.w * k3f.x;
        s[i][1] += qv.x * k0f.y + qv.y * k1f.y + qv.z * k2f.y + qv.w * k3f.y;
        s[i][2] += qv.x * k0f.z + qv.y * k1f.z + qv.z * k2f.z + qv.w * k3f.z;
        s[i][3] += qv.x * k0f.w + qv.y * k1f.w + qv.z * k2f.w + qv.w * k3f.w;
      }
    }

    // mask + online softmax (row group = 16 lanes sharing ty → width-16 shfl)
#pragma unroll
    for (int i = 0; i < 8; i++) {
      float4 mm =
          *(const float4*)(maskBase + (size_t)(ty * 8 + i) * S_ + k0 + tx * 4);
      s[i][0] = s[i][0] * 0.125f - 1e6f * mm.x;
      s[i][1] = s[i][1] * 0.125f - 1e6f * mm.y;
      s[i][2] = s[i][2] * 0.125f - 1e6f * mm.z;
      s[i][3] = s[i][3] * 0.125f - 1e6f * mm.w;

      float mx = fmaxf(fmaxf(s[i][0], s[i][1]), fmaxf(s[i][2], s[i][3]));
      mx = fmaxf(mx, __shfl_xor_sync(0xffffffffu, mx, 1, 16));
      mx = fmaxf(mx, __shfl_xor_sync(0xffffffffu, mx, 2, 16));
      mx = fmaxf(mx, __shfl_xor_sync(0xffffffffu, mx, 4, 16));
      mx = fmaxf(mx, __shfl_xor_sync(0xffffffffu, mx, 8, 16));

      float mn = fmaxf(m[i], mx);
      float f = __expf(m[i] - mn);
      m[i] = mn;

      float rs = 0.f;
      s[i][0] = __expf(s[i][0] - mn); rs += s[i][0];
      s[i][1] = __expf(s[i][1] - mn); rs += s[i][1];
      s[i][2] = __expf(s[i][2] - mn); rs += s[i][2];
      s[i][3] = __expf(s[i][3] - mn); rs += s[i][3];
      rs += __shfl_xor_sync(0xffffffffu, rs, 1, 16);
      rs += __shfl_xor_sync(0xffffffffu, rs, 2, 16);
      rs += __shfl_xor_sync(0xffffffffu, rs, 4, 16);
      rs += __shfl_xor_sync(0xffffffffu, rs, 8, 16);

      lsum[i] = lsum[i] * f + rs;
      o[i][0] *= f;
      o[i][1] *= f;
      o[i][2] *= f;
      o[i][3] *= f;
    }

    __syncthreads();  // all Kt reads done before P overwrite
#pragma unroll
    for (int i = 0; i < 8; i++) {
      *(float4*)&KP[(ty * 8 + i) * PP + tx * 4] =
          make_float4(s[i][0], s[i][1], s[i][2], s[i][3]);
    }
    __syncthreads();

    // PV: o[i][j] += sum_k P[ty*8+i][k] * V[k][tx*4+j]  (4-k chunks, all f4)
#pragma unroll 2
    for (int k4 = 0; k4 < KT; k4 += 4) {
      const float* vp = &Vs[k4 * PVP + tx * 4];
      float4 v0 = *(const float4*)(vp);
      float4 v1 = *(const float4*)(vp + PVP);
      float4 v2 = *(const float4*)(vp + 2 * PVP);
      float4 v3 = *(const float4*)(vp + 3 * PVP);
#pragma unroll
      for (int i = 0; i < 8; i++) {
        float4 pv = *(const float4*)&KP[(ty * 8 + i) * PP + k4];
        o[i][0] += pv.x * v0.x + pv.y * v1.x + pv.z * v2.x + pv.w * v3.x;
        o[i][1] += pv.x * v0.y + pv.y * v1.y + pv.z * v2.y + pv.w * v3.y;
        o[i][2] += pv.x * v0.z + pv.y * v1.z + pv.z * v2.z + pv.w * v3.z;
        o[i][3] += pv.x * v0.w + pv.y * v1.w + pv.z * v2.w + pv.w * v3.w;
      }
    }
  }

  // normalize + store merged-head output [B,S,D]
#pragma unroll
  for (int i = 0; i < 8; i++) {
    float inv = 1.f / lsum[i];
    float4 r = make_float4(o[i][0] * inv, o[i][1] * inv, o[i][2] * inv,
                           o[i][3] * inv);
    *(float4*)(Out + base + (size_t)(q0 + ty * 8 + i) * DM_ + tx * 4) = r;
  }
}

// ---------------- launch ----------------
extern "C" void kernel_launch(void* const* d_in, const int* in_sizes, int n_in,
                              void* d_out, int out_size) {
  const float* q_in = (const float*)d_in[0];
  const float* k_in = (const float*)d_in[1];
  const float* v_in = (const float*)d_in[2];
  const float* m_in = (const float*)d_in[3];
  const float* Wq = (const float*)d_in[4];
  const float* bq = (const float*)d_in[5];
  const float* Wk = (const float*)d_in[6];
  const float* bk = (const float*)d_in[7];
  const float* Wv = (const float*)d_in[8];
  const float* bv = (const float*)d_in[9];
  const float* Wo = (const float*)d_in[10];
  const float* bo = (const float*)d_in[11];
  float* out = (float*)d_out;

  float *Qp, *Kp, *Vp, *Ap;
  cudaGetSymbolAddress((void**)&Qp, g_Q);
  cudaGetSymbolAddress((void**)&Kp, g_K);
  cudaGetSymbolAddress((void**)&Vp, g_V);
  cudaGetSymbolAddress((void**)&Ap, g_attn);

  cudaFuncSetAttribute(gemm_tf32_kernel,
                       cudaFuncAttributeMaxDynamicSharedMemorySize,
                       GEMM_SMEM_BYTES);
  cudaFuncSetAttribute(attn_kernel, cudaFuncAttributeMaxDynamicSharedMemorySize,
                       ATTN_SMEM_BYTES);

  dim3 gb(DM_ / GBN, (B_ * S_) / GBM);
  gemm_tf32_kernel<<<gb, 256, GEMM_SMEM_BYTES>>>(q_in, Wq, bq, Qp);
  gemm_tf32_kernel<<<gb, 256, GEMM_SMEM_BYTES>>>(k_in, Wk, bk, Kp);
  gemm_tf32_kernel<<<gb, 256, GEMM_SMEM_BYTES>>>(v_in, Wv, bv, Vp);

  dim3 ga(S_ / QT, H_, B_);
  attn_kernel<<<ga, 256, ATTN_SMEM_BYTES>>>(Qp, Kp, Vp, m_in, Ap);

  gemm_tf32_kernel<<<gb, 256, GEMM_SMEM_BYTES>>>(Ap, Wo, bo, out);
}